// round 7
// baseline (speedup 1.0000x reference)
#include <cuda_runtime.h>
#include <math.h>

#define B 192
#define D 2048
#define H 128
#define LOG2PI 1.8378770664093453f
#define IG 4   // i-rows per main-kernel block

// Scratch (device globals — no allocation allowed)
__device__ __align__(16) float g_h1[B * 2 * H];
__device__ __align__(16) float g_mu[B * D];
__device__ __align__(16) float g_scale[B * D];
__device__ float g_lvpart[B * 8];

// ---------------------------------------------------------------------------
// Kernel 1: h1 = relu(q @ w1^T + b1), both heads (cols 0..127 mu, 128..255 lv).
// 8x4 register-tiled warps: warp computes 8 rows x 4 cols, lanes split K=2048.
// grid = (8 colgroups-of-8warps, 24 rowgroups) x 256 threads = 192 blocks.
// ---------------------------------------------------------------------------
__global__ void __launch_bounds__(256) gemm1_kernel(
    const float* __restrict__ q,
    const float* __restrict__ mw, const float* __restrict__ mb,
    const float* __restrict__ lw, const float* __restrict__ lb)
{
    int warp = threadIdx.x >> 5;
    int lane = threadIdx.x & 31;
    int cg   = blockIdx.x * 8 + warp;   // colgroup 0..63
    int row0 = blockIdx.y * 8;
    int col0 = cg * 4;

    const float* wbase;
    const float* bbase;
    int clocal;
    if (col0 < H) { wbase = mw; bbase = mb; clocal = col0;     }
    else          { wbase = lw; bbase = lb; clocal = col0 - H; }

    const float4* q4 = (const float4*)q;
    const float4* w4 = (const float4*)wbase;

    float acc[8][4];
    #pragma unroll
    for (int r = 0; r < 8; ++r)
        #pragma unroll
        for (int c = 0; c < 4; ++c) acc[r][c] = 0.f;

    #pragma unroll 4
    for (int it = 0; it < (D / 4) / 32; ++it) {   // 16 iters
        int k4 = lane + it * 32;
        float4 b[4];
        #pragma unroll
        for (int c = 0; c < 4; ++c) b[c] = w4[(size_t)(clocal + c) * (D / 4) + k4];
        #pragma unroll
        for (int r = 0; r < 8; ++r) {
            float4 a = q4[(size_t)(row0 + r) * (D / 4) + k4];
            #pragma unroll
            for (int c = 0; c < 4; ++c)
                acc[r][c] += a.x * b[c].x + a.y * b[c].y
                           + a.z * b[c].z + a.w * b[c].w;
        }
    }

    float bv[4];
    #pragma unroll
    for (int c = 0; c < 4; ++c) bv[c] = bbase[clocal + c];

    #pragma unroll
    for (int r = 0; r < 8; ++r)
        #pragma unroll
        for (int c = 0; c < 4; ++c) {
            float v = acc[r][c];
            #pragma unroll
            for (int o = 16; o; o >>= 1) v += __shfl_xor_sync(0xffffffffu, v, o);
            if (lane == 0)
                g_h1[(row0 + r) * 256 + col0 + c] = fmaxf(v + bv[c], 0.f);
        }
}

// ---------------------------------------------------------------------------
// Kernel 2 (fused layers 2+3): per block = (head, 256-col d-tile, 8 rows).
// Heads are independent chains, so each block recomputes its own h2 from h1
// in smem (8x redundant across the 8 d-tiles; ~3us chip-wide) and saves a
// kernel launch + the g_h2 global round-trip.
//   step 1: sh1[8][128]  <- h1 half-rows
//   step 2: sh2[8][128]  <- relu(sh1 @ w2^T + b2)     (thread = (col, 4-rows))
//   step 3: out[d]       <- relu(sh2 @ w3row + b3)
//     mu head  (bx 0..7):  g_mu
//     lv head  (bx 8..15): g_scale = exp(0.25*lv) + deterministic sum(lv)
// grid = (16, 24) x 256 threads.
// ---------------------------------------------------------------------------
__global__ void __launch_bounds__(256) gemm23_kernel(
    const float* __restrict__ mw2, const float* __restrict__ mb2,
    const float* __restrict__ lw2, const float* __restrict__ lb2,
    const float* __restrict__ mw3, const float* __restrict__ mb3,
    const float* __restrict__ lw3, const float* __restrict__ lb3)
{
    __shared__ float  sh1[8][H];
    __shared__ float4 sh2[8][H / 4];
    __shared__ float  red[8][8];

    int tid  = threadIdx.x;
    int row0 = blockIdx.y * 8;
    int head = blockIdx.x >> 3;        // 0 = mu, 1 = lv

    // step 1: load h1 half-rows (8 x 128)
    #pragma unroll
    for (int i = 0; i < 4; ++i) {
        int idx = tid + i * 256;       // 0..1023
        int r = idx >> 7, k = idx & 127;
        sh1[r][k] = g_h1[(row0 + r) * 256 + head * H + k];
    }
    __syncthreads();

    // step 2: h2 = relu(h1 @ w2^T + b2). thread -> (col c, 4 rows)
    {
        const float* w2 = head ? lw2 : mw2;
        const float* b2 = head ? lb2 : mb2;
        int c    = tid & 127;
        int rgrp = tid >> 7;           // 0 or 1 -> rows rgrp*4..+3
        const float* wr = w2 + (size_t)c * H;
        float a0, a1, a2, a3;
        a0 = a1 = a2 = a3 = b2[c];
        #pragma unroll 8
        for (int k = 0; k < H; ++k) {
            float wv = wr[k];
            a0 += sh1[rgrp * 4 + 0][k] * wv;
            a1 += sh1[rgrp * 4 + 1][k] * wv;
            a2 += sh1[rgrp * 4 + 2][k] * wv;
            a3 += sh1[rgrp * 4 + 3][k] * wv;
        }
        float* sh2f = (float*)sh2;
        sh2f[(rgrp * 4 + 0) * H + c] = fmaxf(a0, 0.f);
        sh2f[(rgrp * 4 + 1) * H + c] = fmaxf(a1, 0.f);
        sh2f[(rgrp * 4 + 2) * H + c] = fmaxf(a2, 0.f);
        sh2f[(rgrp * 4 + 3) * H + c] = fmaxf(a3, 0.f);
    }
    __syncthreads();

    // step 3: layer 3 over this block's 256 d-columns
    int d = (blockIdx.x & 7) * 256 + tid;         // 0..2047 within head
    const float* wrow = (head ? lw3 : mw3) + (size_t)d * H;
    const float* bptr = head ? lb3 : mb3;

    float acc[8];
    #pragma unroll
    for (int r = 0; r < 8; ++r) acc[r] = 0.f;

    #pragma unroll
    for (int kk = 0; kk < 32; ++kk) {
        float4 w = ((const float4*)wrow)[kk];
        #pragma unroll
        for (int r = 0; r < 8; ++r) {
            float4 h = sh2[r][kk];
            acc[r] += w.x * h.x + w.y * h.y + w.z * h.z + w.w * h.w;
        }
    }
    float bias = bptr[d];

    if (!head) {
        #pragma unroll
        for (int r = 0; r < 8; ++r)
            g_mu[(size_t)(row0 + r) * D + d] = fmaxf(acc[r] + bias, 0.f);
    } else {
        int lane = tid & 31, wid = tid >> 5;
        #pragma unroll
        for (int r = 0; r < 8; ++r) {
            float v = fmaxf(acc[r] + bias, 0.f);
            g_scale[(size_t)(row0 + r) * D + d] = expf(0.25f * v);
            #pragma unroll
            for (int o = 16; o; o >>= 1) v += __shfl_xor_sync(0xffffffffu, v, o);
            if (lane == 0) red[wid][r] = v;
        }
        __syncthreads();
        if (tid == 0) {
            #pragma unroll
            for (int r = 0; r < 8; ++r) {
                float sum = 0.f;
                #pragma unroll
                for (int k = 0; k < 8; ++k) sum += red[k][r];
                g_lvpart[(row0 + r) * 8 + (blockIdx.x & 7)] = sum;
            }
        }
    }
}

// ---------------------------------------------------------------------------
// Kernel 3 (HBM-bound mainloop): block per (j, 4 i-rows), 256 threads,
// 2 float4 per thread per row (8 independent loads in flight), mu/scale in
// registers. minBlocksPerSM=6 forces regs<=42 -> 48 warps/SM for latency hiding.
// ---------------------------------------------------------------------------
__global__ void __launch_bounds__(256, 6) main_kernel(
    const float* __restrict__ eps,
    float* __restrict__ p,
    float* __restrict__ lp)
{
    __shared__ float red[8][IG];
    __shared__ float s_t;

    int j   = blockIdx.x % B;
    int ig  = blockIdx.x / B;
    int tid = threadIdx.x;

    const float4* m4 = (const float4*)g_mu    + (size_t)j * (D / 4);
    const float4* s4 = (const float4*)g_scale + (size_t)j * (D / 4);
    float4 m0 = m4[tid], m1 = m4[tid + 256];
    float4 s0 = s4[tid], s1 = s4[tid + 256];

    if (tid == 0) {
        float sum = 0.f;
        #pragma unroll
        for (int k = 0; k < 8; ++k) sum += g_lvpart[j * 8 + k];
        s_t = -0.25f * sum - 0.5f * (float)D * LOG2PI;
    }

    float acc[IG];
    #pragma unroll
    for (int r = 0; r < IG; ++r) {
        size_t row = (size_t)(ig * IG + r) * B + j;
        const float4* e4 = (const float4*)eps + row * (D / 4);
        float4*       p4 = (float4*)p        + row * (D / 4);

        float4 e0 = __ldcs(&e4[tid]);
        float4 e1 = __ldcs(&e4[tid + 256]);
        float4 o0, o1;
        o0.x = fmaf(e0.x, s0.x, m0.x);
        o0.y = fmaf(e0.y, s0.y, m0.y);
        o0.z = fmaf(e0.z, s0.z, m0.z);
        o0.w = fmaf(e0.w, s0.w, m0.w);
        o1.x = fmaf(e1.x, s1.x, m1.x);
        o1.y = fmaf(e1.y, s1.y, m1.y);
        o1.z = fmaf(e1.z, s1.z, m1.z);
        o1.w = fmaf(e1.w, s1.w, m1.w);
        __stcs(&p4[tid], o0);
        __stcs(&p4[tid + 256], o1);
        acc[r] = e0.x * e0.x + e0.y * e0.y + e0.z * e0.z + e0.w * e0.w
               + e1.x * e1.x + e1.y * e1.y + e1.z * e1.z + e1.w * e1.w;
    }

    int lane = tid & 31, wid = tid >> 5;
    #pragma unroll
    for (int r = 0; r < IG; ++r) {
        float v = acc[r];
        #pragma unroll
        for (int o = 16; o; o >>= 1) v += __shfl_xor_sync(0xffffffffu, v, o);
        if (lane == 0) red[wid][r] = v;
    }
    __syncthreads();
    if (tid < IG) {
        float v = 0.f;
        #pragma unroll
        for (int k = 0; k < 8; ++k) v += red[k][tid];
        lp[(size_t)(ig * IG + tid) * B + j] = -0.5f * v + s_t;
    }
}

// ---------------------------------------------------------------------------
extern "C" void kernel_launch(void* const* d_in, const int* in_sizes, int n_in,
                              void* d_out, int out_size)
{
    const float* q     = (const float*)d_in[0];
    const float* eps   = (const float*)d_in[1];
    const float* mu_w1 = (const float*)d_in[2];
    const float* mu_b1 = (const float*)d_in[3];
    const float* mu_w2 = (const float*)d_in[4];
    const float* mu_b2 = (const float*)d_in[5];
    const float* mu_w3 = (const float*)d_in[6];
    const float* mu_b3 = (const float*)d_in[7];
    const float* lv_w1 = (const float*)d_in[8];
    const float* lv_b1 = (const float*)d_in[9];
    const float* lv_w2 = (const float*)d_in[10];
    const float* lv_b2 = (const float*)d_in[11];
    const float* lv_w3 = (const float*)d_in[12];
    const float* lv_b3 = (const float*)d_in[13];

    float* p  = (float*)d_out;                       // [B, B, D]
    float* lp = (float*)d_out + (size_t)B * B * D;   // [B, B]

    gemm1_kernel<<<dim3(8, 24), 256>>>(q, mu_w1, mu_b1, lv_w1, lv_b1);
    gemm23_kernel<<<dim3(16, 24), 256>>>(mu_w2, mu_b2, lv_w2, lv_b2,
                                         mu_w3, mu_b3, lv_w3, lv_b3);
    main_kernel<<<B * (B / IG), 256>>>(eps, p, lp);
}